// round 7
// baseline (speedup 1.0000x reference)
#include <cuda_runtime.h>
#include <math.h>

#define S 2048
#define B 2
#define STILE 4
#define QK_THREADS 512
#define QK_BLOCKS 148

// Scratch for normalized q and k: [which(q=0,k=1)][b][n][blade] = 256 KB
__device__ __align__(256) float g_qk[2][B][S][8];

// 256-bit global store, streaming (evict-first): output is never re-read.
__device__ __forceinline__ void stg256_cs(float* p, const float4& a, const float4& b)
{
    asm volatile("st.global.cs.v8.f32 [%0], {%1,%2,%3,%4,%5,%6,%7,%8};"
                 :: "l"(p),
                    "f"(a.x), "f"(a.y), "f"(a.z), "f"(a.w),
                    "f"(b.x), "f"(b.y), "f"(b.z), "f"(b.w)
                 : "memory");
}

__device__ __forceinline__ void ldg256(const float* p, float4& a, float4& b)
{
    asm volatile("ld.global.nc.v8.f32 {%0,%1,%2,%3,%4,%5,%6,%7}, [%8];"
                 : "=f"(a.x), "=f"(a.y), "=f"(a.z), "=f"(a.w),
                   "=f"(b.x), "=f"(b.y), "=f"(b.z), "=f"(b.w)
                 : "l"(p));
}

// ---------------------------------------------------------------------------
// Kernel 1 (persistent, software-pipelined): q/k = normalize(mv_linear(x,W),a)
// 148 blocks x 512 threads; x slice register-resident. Per row: FMA phase,
// then PREFETCH next row's W (hidden behind reduction), butterfly, ONE
// barrier, warp-0 epilogue. red[] double-buffered.
// ---------------------------------------------------------------------------
__global__ __launch_bounds__(QK_THREADS) void qk_kernel(
    const float* __restrict__ x,    // (B, S, 8)
    const float* __restrict__ Wq,   // (S, S, 4)
    const float* __restrict__ Wk,   // (S, S, 4)
    const float* __restrict__ a)    // (3000, 4)
{
    const int tid  = threadIdx.x;
    const int warp = tid >> 5, lane = tid & 31;

    // x slice into registers: xr[j] = {b0 lo, b0 hi, b1 lo, b1 hi} for m_j
    float4 xr[4][4];
#pragma unroll
    for (int j = 0; j < 4; j++) {
        const int m = tid + QK_THREADS * j;
        ldg256(x + (size_t)m * 8,       xr[j][0], xr[j][1]);
        ldg256(x + (size_t)(S + m) * 8, xr[j][2], xr[j][3]);
    }

    __shared__ float red[2][QK_THREADS / 32][32];
    __shared__ float vals[32];
    __shared__ float denom[2][B][4];

    // Preload first row's W
    float4 wq[4], wk[4];
    {
        const float4* WqR = reinterpret_cast<const float4*>(Wq + (size_t)blockIdx.x * S * 4);
        const float4* WkR = reinterpret_cast<const float4*>(Wk + (size_t)blockIdx.x * S * 4);
#pragma unroll
        for (int j = 0; j < 4; j++) {
            wq[j] = __ldcs(&WqR[tid + QK_THREADS * j]);
            wk[j] = __ldcs(&WkR[tid + QK_THREADS * j]);
        }
    }

    int p = 0;
    for (int n = blockIdx.x; n < S; n += QK_BLOCKS) {
        // v[0..15] = q accumulators, v[16..31] = k accumulators
        float v[32];
#pragma unroll
        for (int i = 0; i < 32; i++) v[i] = 0.f;

#pragma unroll
        for (int j = 0; j < 4; j++) {
            const float4 x0a = xr[j][0], x0b = xr[j][1];
            const float4 x1a = xr[j][2], x1b = xr[j][3];
            const float4 q4 = wq[j], k4 = wk[j];

            v[0]  = fmaf(q4.x, x0a.x, v[0]);
            v[1]  = fmaf(q4.y, x0a.y, v[1]);
            v[2]  = fmaf(q4.y, x0a.z, v[2]);
            v[3]  = fmaf(q4.y, x0a.w, v[3]);
            v[4]  = fmaf(q4.z, x0b.x, v[4]);
            v[5]  = fmaf(q4.z, x0b.y, v[5]);
            v[6]  = fmaf(q4.z, x0b.z, v[6]);
            v[7]  = fmaf(q4.w, x0b.w, v[7]);
            v[8]  = fmaf(q4.x, x1a.x, v[8]);
            v[9]  = fmaf(q4.y, x1a.y, v[9]);
            v[10] = fmaf(q4.y, x1a.z, v[10]);
            v[11] = fmaf(q4.y, x1a.w, v[11]);
            v[12] = fmaf(q4.z, x1b.x, v[12]);
            v[13] = fmaf(q4.z, x1b.y, v[13]);
            v[14] = fmaf(q4.z, x1b.z, v[14]);
            v[15] = fmaf(q4.w, x1b.w, v[15]);

            v[16] = fmaf(k4.x, x0a.x, v[16]);
            v[17] = fmaf(k4.y, x0a.y, v[17]);
            v[18] = fmaf(k4.y, x0a.z, v[18]);
            v[19] = fmaf(k4.y, x0a.w, v[19]);
            v[20] = fmaf(k4.z, x0b.x, v[20]);
            v[21] = fmaf(k4.z, x0b.y, v[21]);
            v[22] = fmaf(k4.z, x0b.z, v[22]);
            v[23] = fmaf(k4.w, x0b.w, v[23]);
            v[24] = fmaf(k4.x, x1a.x, v[24]);
            v[25] = fmaf(k4.y, x1a.y, v[25]);
            v[26] = fmaf(k4.y, x1a.z, v[26]);
            v[27] = fmaf(k4.y, x1a.w, v[27]);
            v[28] = fmaf(k4.z, x1b.x, v[28]);
            v[29] = fmaf(k4.z, x1b.y, v[29]);
            v[30] = fmaf(k4.z, x1b.z, v[30]);
            v[31] = fmaf(k4.w, x1b.w, v[31]);
        }

        // PREFETCH next row's W — latency hidden behind reduction + barrier.
        const int nn = n + QK_BLOCKS;
        if (nn < S) {
            const float4* WqR = reinterpret_cast<const float4*>(Wq + (size_t)nn * S * 4);
            const float4* WkR = reinterpret_cast<const float4*>(Wk + (size_t)nn * S * 4);
#pragma unroll
            for (int j = 0; j < 4; j++) {
                wq[j] = __ldcs(&WqR[tid + QK_THREADS * j]);
                wk[j] = __ldcs(&WkR[tid + QK_THREADS * j]);
            }
        }

        // Multi-value butterfly: lane L ends with full warp sum of acc L.
#pragma unroll
        for (int d = 16; d >= 1; d >>= 1) {
#pragma unroll
            for (int i = 0; i < d; i++) {
                const bool hi = (lane & d) != 0;
                const float keep = hi ? v[i + d] : v[i];
                const float send = hi ? v[i] : v[i + d];
                v[i] = keep + __shfl_xor_sync(0xffffffffu, send, d);
            }
        }
        red[p][warp][lane] = v[0];
        __syncthreads();

        // Epilogue entirely inside warp 0
        if (tid < 32) {
            float s = 0.f;
#pragma unroll
            for (int w2 = 0; w2 < QK_THREADS / 32; w2++) s += red[p][w2][tid];
            vals[tid] = s;
            __syncwarp();

            if (tid < 4) {
                const int which = tid >> 1, b = tid & 1;
                const float* vv = &vals[which * 16 + b * 8];
                float nr[4];
                nr[0] = fabsf(vv[0]);
                nr[1] = sqrtf(vv[1] * vv[1] + vv[2] * vv[2] + vv[3] * vv[3]);
                nr[2] = sqrtf(vv[4] * vv[4] + vv[5] * vv[5] + vv[6] * vv[6]);
                nr[3] = fabsf(vv[7]);
#pragma unroll
                for (int g = 0; g < 4; g++) {
                    float sa = 1.f / (1.f + expf(-a[n * 4 + g]));
                    denom[which][b][g] = sa * (nr[g] - 1.f) + 1.f + 1e-6f;
                }
            }
            __syncwarp();

            const int which = tid >> 4, r = tid & 15;
            const int b = r >> 3, i = r & 7;
            const int g = (i == 0) ? 0 : (i < 4) ? 1 : (i < 7) ? 2 : 3;
            g_qk[which][b][n][i] = vals[tid] / denom[which][b][g];
        }
        p ^= 1;   // no trailing barrier: red double-buffered
    }
}

// ---------------------------------------------------------------------------
// Kernel 2: out[b,s,t,:] = q[b,s,:] (geometric product) k[b,t,:]
// 256-bit K loads, 256-bit streaming stores.
// ---------------------------------------------------------------------------
__global__ __launch_bounds__(256) void gp_kernel(float* __restrict__ out)
{
    const int s0  = blockIdx.x * STILE;
    const int b   = blockIdx.y;
    const int tid = threadIdx.x;

    float q[STILE][8];
#pragma unroll
    for (int si = 0; si < STILE; si++) {
        const float4 qa = *reinterpret_cast<const float4*>(&g_qk[0][b][s0 + si][0]);
        const float4 qb = *reinterpret_cast<const float4*>(&g_qk[0][b][s0 + si][4]);
        q[si][0] = qa.x; q[si][1] = qa.y; q[si][2] = qa.z; q[si][3] = qa.w;
        q[si][4] = qb.x; q[si][5] = qb.y; q[si][6] = qb.z; q[si][7] = qb.w;
    }

    const float* K = &g_qk[1][b][0][0];
    float* obase = out + (((size_t)b * S + s0) * S) * 8;

#pragma unroll
    for (int it = 0; it < 8; it++) {
        const int t = tid + it * 256;
        float4 ka, kb;
        ldg256(K + (size_t)t * 8, ka, kb);
        const float k0 = ka.x, k1 = ka.y, k2 = ka.z, k3 = ka.w;
        const float k4 = kb.x, k5 = kb.y, k6 = kb.z, k7 = kb.w;

#pragma unroll
        for (int si = 0; si < STILE; si++) {
            const float q0 = q[si][0], q1 = q[si][1], q2 = q[si][2], q3 = q[si][3];
            const float q4 = q[si][4], q5 = q[si][5], q6 = q[si][6], q7 = q[si][7];

            float4 o_lo, o_hi;
            o_lo.x = q0*k0 + q1*k1 + q2*k2 + q3*k3 - q4*k4 - q5*k5 - q6*k6 - q7*k7;
            o_lo.y = q0*k1 + q1*k0 - q2*k4 + q4*k2 - q3*k5 + q5*k3 - q6*k7 - q7*k6;
            o_lo.z = q0*k2 + q2*k0 + q1*k4 - q4*k1 - q3*k6 + q6*k3 + q5*k7 + q7*k5;
            o_lo.w = q0*k3 + q3*k0 + q1*k5 - q5*k1 + q2*k6 - q6*k2 - q4*k7 - q7*k4;
            o_hi.x = q0*k4 + q4*k0 + q1*k2 - q2*k1 + q3*k7 + q7*k3 - q5*k6 + q6*k5;
            o_hi.y = q0*k5 + q5*k0 + q1*k3 - q3*k1 - q2*k7 - q7*k2 + q4*k6 - q6*k4;
            o_hi.z = q0*k6 + q6*k0 + q2*k3 - q3*k2 + q1*k7 + q7*k1 - q4*k5 + q5*k4;
            o_hi.w = q0*k7 + q7*k0 + q1*k6 + q6*k1 - q2*k5 - q5*k2 + q3*k4 + q4*k3;

            stg256_cs(obase + (size_t)si * S * 8 + t * 8, o_lo, o_hi);
        }
    }
}

extern "C" void kernel_launch(void* const* d_in, const int* in_sizes, int n_in,
                              void* d_out, int out_size)
{
    const float* x  = (const float*)d_in[0];   // (2, 2048, 8)
    const float* Wq = (const float*)d_in[1];   // (2048, 2048, 4)
    const float* Wk = (const float*)d_in[2];   // (2048, 2048, 4)
    const float* a  = (const float*)d_in[3];   // (3000, 4)
    float* out = (float*)d_out;                // (2, 2048, 2048, 8)

    qk_kernel<<<QK_BLOCKS, QK_THREADS>>>(x, Wq, Wk, a);
    gp_kernel<<<dim3(S / STILE, B), 256>>>(out);
}

// round 8
// speedup vs baseline: 1.0314x; 1.0314x over previous
#include <cuda_runtime.h>
#include <math.h>

#define S 2048
#define B 2
#define STILE 4
#define QK_THREADS 512
#define QK_BLOCKS 148

// Normalized q and k: [which(q=0,k=1)][b][n][blade] = 256 KB
__device__ __align__(256) float g_qk[2][B][S][8];
// Per-warp partial sums: [row][warp][32 vals: 0-15 q(b0,b1), 16-31 k] = 4 MB
__device__ __align__(256) float g_part[S][16][32];

// 256-bit global store, streaming (evict-first): output is never re-read.
__device__ __forceinline__ void stg256_cs(float* p, const float4& a, const float4& b)
{
    asm volatile("st.global.cs.v8.f32 [%0], {%1,%2,%3,%4,%5,%6,%7,%8};"
                 :: "l"(p),
                    "f"(a.x), "f"(a.y), "f"(a.z), "f"(a.w),
                    "f"(b.x), "f"(b.y), "f"(b.z), "f"(b.w)
                 : "memory");
}

__device__ __forceinline__ void ldg256(const float* p, float4& a, float4& b)
{
    asm volatile("ld.global.nc.v8.f32 {%0,%1,%2,%3,%4,%5,%6,%7}, [%8];"
                 : "=f"(a.x), "=f"(a.y), "=f"(a.z), "=f"(a.w),
                   "=f"(b.x), "=f"(b.y), "=f"(b.z), "=f"(b.w)
                 : "l"(p));
}

// ---------------------------------------------------------------------------
// Kernel 1a (persistent, BARRIER-FREE): per-warp partial sums of mv_linear.
// 148 blocks x 512 threads. Thread t owns m in [4t, 4t+4); x slice (64 f)
// register-resident. Per row: 4 LDG.256 (W), 64+64 FMAs, two 16-value
// butterflies, two 64B stores of per-warp partials. No smem, no syncthreads.
// ---------------------------------------------------------------------------
__global__ __launch_bounds__(QK_THREADS) void qk_main(
    const float* __restrict__ x,    // (B, S, 8)
    const float* __restrict__ Wq,   // (S, S, 4)
    const float* __restrict__ Wk)   // (S, S, 4)
{
    const int tid  = threadIdx.x;
    const int warp = tid >> 5, lane = tid & 31;
    const int m0   = tid * 4;

    // x slice: xr[j][0..1] = x[b0][m0+j], xr[j][2..3] = x[b1][m0+j]
    float4 xr[4][4];
#pragma unroll
    for (int j = 0; j < 4; j++) {
        ldg256(x + (size_t)(m0 + j) * 8,     xr[j][0], xr[j][1]);
        ldg256(x + (size_t)(S + m0 + j) * 8, xr[j][2], xr[j][3]);
    }

    for (int n = blockIdx.x; n < S; n += QK_BLOCKS) {
        // W row chunk for this thread: 16 floats per matrix (= 4 m-values)
        const float* WqR = Wq + (size_t)n * S * 4 + m0 * 4;
        const float* WkR = Wk + (size_t)n * S * 4 + m0 * 4;
        float4 wq[4], wk[4];
        ldg256(WqR,     wq[0], wq[1]);
        ldg256(WqR + 8, wq[2], wq[3]);
        ldg256(WkR,     wk[0], wk[1]);
        ldg256(WkR + 8, wk[2], wk[3]);

        // ---- q phase: v[0..7]=b0 blades, v[8..15]=b1 blades ----
        float v[16];
#pragma unroll
        for (int i = 0; i < 16; i++) v[i] = 0.f;
#pragma unroll
        for (int j = 0; j < 4; j++) {
            const float4 x0a = xr[j][0], x0b = xr[j][1];
            const float4 x1a = xr[j][2], x1b = xr[j][3];
            const float4 w = wq[j];
            v[0]  = fmaf(w.x, x0a.x, v[0]);
            v[1]  = fmaf(w.y, x0a.y, v[1]);
            v[2]  = fmaf(w.y, x0a.z, v[2]);
            v[3]  = fmaf(w.y, x0a.w, v[3]);
            v[4]  = fmaf(w.z, x0b.x, v[4]);
            v[5]  = fmaf(w.z, x0b.y, v[5]);
            v[6]  = fmaf(w.z, x0b.z, v[6]);
            v[7]  = fmaf(w.w, x0b.w, v[7]);
            v[8]  = fmaf(w.x, x1a.x, v[8]);
            v[9]  = fmaf(w.y, x1a.y, v[9]);
            v[10] = fmaf(w.y, x1a.z, v[10]);
            v[11] = fmaf(w.y, x1a.w, v[11]);
            v[12] = fmaf(w.z, x1b.x, v[12]);
            v[13] = fmaf(w.z, x1b.y, v[13]);
            v[14] = fmaf(w.z, x1b.z, v[14]);
            v[15] = fmaf(w.w, x1b.w, v[15]);
        }
        // 16-value butterfly: lane L ends with warp-half sum of value L&15;
        // final xor-16 merges the halves -> full warp sum, duplicated.
#pragma unroll
        for (int d = 8; d >= 1; d >>= 1) {
#pragma unroll
            for (int i = 0; i < d; i++) {
                const bool hi = (lane & d) != 0;
                const float keep = hi ? v[i + d] : v[i];
                const float send = hi ? v[i] : v[i + d];
                v[i] = keep + __shfl_xor_sync(0xffffffffu, send, d);
            }
        }
        v[0] += __shfl_xor_sync(0xffffffffu, v[0], 16);
        if (lane < 16) g_part[n][warp][lane] = v[0];

        // ---- k phase ----
#pragma unroll
        for (int i = 0; i < 16; i++) v[i] = 0.f;
#pragma unroll
        for (int j = 0; j < 4; j++) {
            const float4 x0a = xr[j][0], x0b = xr[j][1];
            const float4 x1a = xr[j][2], x1b = xr[j][3];
            const float4 w = wk[j];
            v[0]  = fmaf(w.x, x0a.x, v[0]);
            v[1]  = fmaf(w.y, x0a.y, v[1]);
            v[2]  = fmaf(w.y, x0a.z, v[2]);
            v[3]  = fmaf(w.y, x0a.w, v[3]);
            v[4]  = fmaf(w.z, x0b.x, v[4]);
            v[5]  = fmaf(w.z, x0b.y, v[5]);
            v[6]  = fmaf(w.z, x0b.z, v[6]);
            v[7]  = fmaf(w.w, x0b.w, v[7]);
            v[8]  = fmaf(w.x, x1a.x, v[8]);
            v[9]  = fmaf(w.y, x1a.y, v[9]);
            v[10] = fmaf(w.y, x1a.z, v[10]);
            v[11] = fmaf(w.y, x1a.w, v[11]);
            v[12] = fmaf(w.z, x1b.x, v[12]);
            v[13] = fmaf(w.z, x1b.y, v[13]);
            v[14] = fmaf(w.z, x1b.z, v[14]);
            v[15] = fmaf(w.w, x1b.w, v[15]);
        }
#pragma unroll
        for (int d = 8; d >= 1; d >>= 1) {
#pragma unroll
            for (int i = 0; i < d; i++) {
                const bool hi = (lane & d) != 0;
                const float keep = hi ? v[i + d] : v[i];
                const float send = hi ? v[i] : v[i + d];
                v[i] = keep + __shfl_xor_sync(0xffffffffu, send, d);
            }
        }
        v[0] += __shfl_xor_sync(0xffffffffu, v[0], 16);
        if (lane < 16) g_part[n][warp][16 + lane] = v[0];
    }
}

// ---------------------------------------------------------------------------
// Kernel 1b: reduce 16 warp-partials per row, normalize, write g_qk.
// One warp per row; lane = value index (which,b,i).
// ---------------------------------------------------------------------------
__global__ __launch_bounds__(256) void qk_fix(const float* __restrict__ a)
{
    const int n = blockIdx.x * 8 + (threadIdx.x >> 5);
    const int v = threadIdx.x & 31;

    float s = 0.f;
#pragma unroll
    for (int p = 0; p < 16; p++) s += g_part[n][p][v];

    // Gather the 8 blade values of this lane's (which,b) group via shuffles.
    const int base = v & ~7;
    const float e0 = __shfl_sync(0xffffffffu, s, base + 0);
    const float e1 = __shfl_sync(0xffffffffu, s, base + 1);
    const float e2 = __shfl_sync(0xffffffffu, s, base + 2);
    const float e3 = __shfl_sync(0xffffffffu, s, base + 3);
    const float e4 = __shfl_sync(0xffffffffu, s, base + 4);
    const float e5 = __shfl_sync(0xffffffffu, s, base + 5);
    const float e6 = __shfl_sync(0xffffffffu, s, base + 6);
    const float e7 = __shfl_sync(0xffffffffu, s, base + 7);

    const int which = v >> 4, b = (v >> 3) & 1, i = v & 7;
    const int g = (i == 0) ? 0 : (i < 4) ? 1 : (i < 7) ? 2 : 3;

    float nr;
    if      (g == 0) nr = fabsf(e0);
    else if (g == 1) nr = sqrtf(e1 * e1 + e2 * e2 + e3 * e3);
    else if (g == 2) nr = sqrtf(e4 * e4 + e5 * e5 + e6 * e6);
    else             nr = fabsf(e7);

    const float sa = 1.f / (1.f + expf(-a[n * 4 + g]));
    const float den = sa * (nr - 1.f) + 1.f + 1e-6f;
    g_qk[which][b][n][i] = s / den;
}

// ---------------------------------------------------------------------------
// Kernel 2: out[b,s,t,:] = q[b,s,:] (geometric product) k[b,t,:]
// 256-bit K loads, 256-bit streaming stores.
// ---------------------------------------------------------------------------
__global__ __launch_bounds__(256) void gp_kernel(float* __restrict__ out)
{
    const int s0  = blockIdx.x * STILE;
    const int b   = blockIdx.y;
    const int tid = threadIdx.x;

    float q[STILE][8];
#pragma unroll
    for (int si = 0; si < STILE; si++) {
        const float4 qa = *reinterpret_cast<const float4*>(&g_qk[0][b][s0 + si][0]);
        const float4 qb = *reinterpret_cast<const float4*>(&g_qk[0][b][s0 + si][4]);
        q[si][0] = qa.x; q[si][1] = qa.y; q[si][2] = qa.z; q[si][3] = qa.w;
        q[si][4] = qb.x; q[si][5] = qb.y; q[si][6] = qb.z; q[si][7] = qb.w;
    }

    const float* K = &g_qk[1][b][0][0];
    float* obase = out + (((size_t)b * S + s0) * S) * 8;

#pragma unroll
    for (int it = 0; it < 8; it++) {
        const int t = tid + it * 256;
        float4 ka, kb;
        ldg256(K + (size_t)t * 8, ka, kb);
        const float k0 = ka.x, k1 = ka.y, k2 = ka.z, k3 = ka.w;
        const float k4 = kb.x, k5 = kb.y, k6 = kb.z, k7 = kb.w;

#pragma unroll
        for (int si = 0; si < STILE; si++) {
            const float q0 = q[si][0], q1 = q[si][1], q2 = q[si][2], q3 = q[si][3];
            const float q4 = q[si][4], q5 = q[si][5], q6 = q[si][6], q7 = q[si][7];

            float4 o_lo, o_hi;
            o_lo.x = q0*k0 + q1*k1 + q2*k2 + q3*k3 - q4*k4 - q5*k5 - q6*k6 - q7*k7;
            o_lo.y = q0*k1 + q1*k0 - q2*k4 + q4*k2 - q3*k5 + q5*k3 - q6*k7 - q7*k6;
            o_lo.z = q0*k2 + q2*k0 + q1*k4 - q4*k1 - q3*k6 + q6*k3 + q5*k7 + q7*k5;
            o_lo.w = q0*k3 + q3*k0 + q1*k5 - q5*k1 + q2*k6 - q6*k2 - q4*k7 - q7*k4;
            o_hi.x = q0*k4 + q4*k0 + q1*k2 - q2*k1 + q3*k7 + q7*k3 - q5*k6 + q6*k5;
            o_hi.y = q0*k5 + q5*k0 + q1*k3 - q3*k1 - q2*k7 - q7*k2 + q4*k6 - q6*k4;
            o_hi.z = q0*k6 + q6*k0 + q2*k3 - q3*k2 + q1*k7 + q7*k1 - q4*k5 + q5*k4;
            o_hi.w = q0*k7 + q7*k0 + q1*k6 + q6*k1 - q2*k5 - q5*k2 + q3*k4 + q4*k3;

            stg256_cs(obase + (size_t)si * S * 8 + t * 8, o_lo, o_hi);
        }
    }
}

extern "C" void kernel_launch(void* const* d_in, const int* in_sizes, int n_in,
                              void* d_out, int out_size)
{
    const float* x  = (const float*)d_in[0];   // (2, 2048, 8)
    const float* Wq = (const float*)d_in[1];   // (2048, 2048, 4)
    const float* Wk = (const float*)d_in[2];   // (2048, 2048, 4)
    const float* a  = (const float*)d_in[3];   // (3000, 4)
    float* out = (float*)d_out;                // (2, 2048, 2048, 8)

    qk_main<<<QK_BLOCKS, QK_THREADS>>>(x, Wq, Wk);
    qk_fix<<<S / 8, 256>>>(a);
    gp_kernel<<<dim3(S / STILE, B), 256>>>(out);
}

// round 9
// speedup vs baseline: 1.0905x; 1.0573x over previous
#include <cuda_runtime.h>
#include <math.h>

#define S 2048
#define B 2
#define STILE 4
#define QK_THREADS 512
#define QK_BLOCKS 148

// Normalized q and k: [which(q=0,k=1)][b][n][blade] = 256 KB
__device__ __align__(256) float g_qk[2][B][S][8];
// Per-warp partial sums: [row][warp][32 vals: 0-15 q(b0,b1), 16-31 k] = 4 MB
__device__ __align__(256) float g_part[S][16][32];

// 256-bit global store, streaming (evict-first): output is never re-read.
__device__ __forceinline__ void stg256_cs(float* p, const float4& a, const float4& b)
{
    asm volatile("st.global.cs.v8.f32 [%0], {%1,%2,%3,%4,%5,%6,%7,%8};"
                 :: "l"(p),
                    "f"(a.x), "f"(a.y), "f"(a.z), "f"(a.w),
                    "f"(b.x), "f"(b.y), "f"(b.z), "f"(b.w)
                 : "memory");
}

__device__ __forceinline__ void ldg256(const float* p, float4& a, float4& b)
{
    asm volatile("ld.global.nc.v8.f32 {%0,%1,%2,%3,%4,%5,%6,%7}, [%8];"
                 : "=f"(a.x), "=f"(a.y), "=f"(a.z), "=f"(a.w),
                   "=f"(b.x), "=f"(b.y), "=f"(b.z), "=f"(b.w)
                 : "l"(p));
}

// ---------------------------------------------------------------------------
// Kernel 1a (persistent, barrier-free, cross-row prefetched):
// per-warp partial sums of mv_linear. 148 blocks x 512 threads; thread t owns
// m in [4t, 4t+4); x slice register-resident. wq is reloaded with the NEXT
// row's data immediately after the q-FMA phase (wq dead), wk likewise after
// the k-FMA phase -> W loads stay in flight across reduction/store phases.
// ---------------------------------------------------------------------------
__global__ __launch_bounds__(QK_THREADS) void qk_main(
    const float* __restrict__ x,    // (B, S, 8)
    const float* __restrict__ Wq,   // (S, S, 4)
    const float* __restrict__ Wk)   // (S, S, 4)
{
    const int tid  = threadIdx.x;
    const int warp = tid >> 5, lane = tid & 31;
    const int m0   = tid * 4;

    // x slice: xr[j][0..1] = x[b0][m0+j], xr[j][2..3] = x[b1][m0+j]
    float4 xr[4][4];
#pragma unroll
    for (int j = 0; j < 4; j++) {
        ldg256(x + (size_t)(m0 + j) * 8,     xr[j][0], xr[j][1]);
        ldg256(x + (size_t)(S + m0 + j) * 8, xr[j][2], xr[j][3]);
    }

    const size_t coff = (size_t)m0 * 4;

    // Preload first row's W
    float4 wq[4], wk[4];
    {
        const float* WqR = Wq + (size_t)blockIdx.x * S * 4 + coff;
        const float* WkR = Wk + (size_t)blockIdx.x * S * 4 + coff;
        ldg256(WqR,     wq[0], wq[1]);
        ldg256(WqR + 8, wq[2], wq[3]);
        ldg256(WkR,     wk[0], wk[1]);
        ldg256(WkR + 8, wk[2], wk[3]);
    }

    for (int n = blockIdx.x; n < S; n += QK_BLOCKS) {
        const int nn = n + QK_BLOCKS;

        // ---- q phase: v[0..7]=b0 blades, v[8..15]=b1 blades ----
        float v[16];
#pragma unroll
        for (int i = 0; i < 16; i++) v[i] = 0.f;
#pragma unroll
        for (int j = 0; j < 4; j++) {
            const float4 x0a = xr[j][0], x0b = xr[j][1];
            const float4 x1a = xr[j][2], x1b = xr[j][3];
            const float4 w = wq[j];
            v[0]  = fmaf(w.x, x0a.x, v[0]);
            v[1]  = fmaf(w.y, x0a.y, v[1]);
            v[2]  = fmaf(w.y, x0a.z, v[2]);
            v[3]  = fmaf(w.y, x0a.w, v[3]);
            v[4]  = fmaf(w.z, x0b.x, v[4]);
            v[5]  = fmaf(w.z, x0b.y, v[5]);
            v[6]  = fmaf(w.z, x0b.z, v[6]);
            v[7]  = fmaf(w.w, x0b.w, v[7]);
            v[8]  = fmaf(w.x, x1a.x, v[8]);
            v[9]  = fmaf(w.y, x1a.y, v[9]);
            v[10] = fmaf(w.y, x1a.z, v[10]);
            v[11] = fmaf(w.y, x1a.w, v[11]);
            v[12] = fmaf(w.z, x1b.x, v[12]);
            v[13] = fmaf(w.z, x1b.y, v[13]);
            v[14] = fmaf(w.z, x1b.z, v[14]);
            v[15] = fmaf(w.w, x1b.w, v[15]);
        }

        // PREFETCH next row's Wq (wq regs dead after q-FMAs)
        if (nn < S) {
            const float* WqR = Wq + (size_t)nn * S * 4 + coff;
            ldg256(WqR,     wq[0], wq[1]);
            ldg256(WqR + 8, wq[2], wq[3]);
        }

        // 16-value butterfly; final xor-16 merges halves -> full warp sum.
#pragma unroll
        for (int d = 8; d >= 1; d >>= 1) {
#pragma unroll
            for (int i = 0; i < d; i++) {
                const bool hi = (lane & d) != 0;
                const float keep = hi ? v[i + d] : v[i];
                const float send = hi ? v[i] : v[i + d];
                v[i] = keep + __shfl_xor_sync(0xffffffffu, send, d);
            }
        }
        v[0] += __shfl_xor_sync(0xffffffffu, v[0], 16);
        if (lane < 16) g_part[n][warp][lane] = v[0];

        // ---- k phase ----
#pragma unroll
        for (int i = 0; i < 16; i++) v[i] = 0.f;
#pragma unroll
        for (int j = 0; j < 4; j++) {
            const float4 x0a = xr[j][0], x0b = xr[j][1];
            const float4 x1a = xr[j][2], x1b = xr[j][3];
            const float4 w = wk[j];
            v[0]  = fmaf(w.x, x0a.x, v[0]);
            v[1]  = fmaf(w.y, x0a.y, v[1]);
            v[2]  = fmaf(w.y, x0a.z, v[2]);
            v[3]  = fmaf(w.y, x0a.w, v[3]);
            v[4]  = fmaf(w.z, x0b.x, v[4]);
            v[5]  = fmaf(w.z, x0b.y, v[5]);
            v[6]  = fmaf(w.z, x0b.z, v[6]);
            v[7]  = fmaf(w.w, x0b.w, v[7]);
            v[8]  = fmaf(w.x, x1a.x, v[8]);
            v[9]  = fmaf(w.y, x1a.y, v[9]);
            v[10] = fmaf(w.y, x1a.z, v[10]);
            v[11] = fmaf(w.y, x1a.w, v[11]);
            v[12] = fmaf(w.z, x1b.x, v[12]);
            v[13] = fmaf(w.z, x1b.y, v[13]);
            v[14] = fmaf(w.z, x1b.z, v[14]);
            v[15] = fmaf(w.w, x1b.w, v[15]);
        }

        // PREFETCH next row's Wk (wk regs dead after k-FMAs)
        if (nn < S) {
            const float* WkR = Wk + (size_t)nn * S * 4 + coff;
            ldg256(WkR,     wk[0], wk[1]);
            ldg256(WkR + 8, wk[2], wk[3]);
        }

#pragma unroll
        for (int d = 8; d >= 1; d >>= 1) {
#pragma unroll
            for (int i = 0; i < d; i++) {
                const bool hi = (lane & d) != 0;
                const float keep = hi ? v[i + d] : v[i];
                const float send = hi ? v[i] : v[i + d];
                v[i] = keep + __shfl_xor_sync(0xffffffffu, send, d);
            }
        }
        v[0] += __shfl_xor_sync(0xffffffffu, v[0], 16);
        if (lane < 16) g_part[n][warp][16 + lane] = v[0];
    }
}

// ---------------------------------------------------------------------------
// Kernel 1b: reduce 16 warp-partials per row, normalize, write g_qk.
// One warp per row; lane = value index (which,b,i).
// ---------------------------------------------------------------------------
__global__ __launch_bounds__(256) void qk_fix(const float* __restrict__ a)
{
    const int n = blockIdx.x * 8 + (threadIdx.x >> 5);
    const int v = threadIdx.x & 31;

    float s = 0.f;
#pragma unroll
    for (int p = 0; p < 16; p++) s += g_part[n][p][v];

    // Gather the 8 blade values of this lane's (which,b) group via shuffles.
    const int base = v & ~7;
    const float e0 = __shfl_sync(0xffffffffu, s, base + 0);
    const float e1 = __shfl_sync(0xffffffffu, s, base + 1);
    const float e2 = __shfl_sync(0xffffffffu, s, base + 2);
    const float e3 = __shfl_sync(0xffffffffu, s, base + 3);
    const float e4 = __shfl_sync(0xffffffffu, s, base + 4);
    const float e5 = __shfl_sync(0xffffffffu, s, base + 5);
    const float e6 = __shfl_sync(0xffffffffu, s, base + 6);
    const float e7 = __shfl_sync(0xffffffffu, s, base + 7);

    const int i = v & 7;
    const int g = (i == 0) ? 0 : (i < 4) ? 1 : (i < 7) ? 2 : 3;

    float nr;
    if      (g == 0) nr = fabsf(e0);
    else if (g == 1) nr = sqrtf(e1 * e1 + e2 * e2 + e3 * e3);
    else if (g == 2) nr = sqrtf(e4 * e4 + e5 * e5 + e6 * e6);
    else             nr = fabsf(e7);

    const float sa = 1.f / (1.f + expf(-a[n * 4 + g]));
    const float den = sa * (nr - 1.f) + 1.f + 1e-6f;

    const int which = v >> 4, b = (v >> 3) & 1;
    g_qk[which][b][n][i] = s / den;
}

// ---------------------------------------------------------------------------
// Kernel 2: out[b,s,t,:] = q[b,s,:] (geometric product) k[b,t,:]
// 256-bit K loads, 256-bit streaming stores.
// ---------------------------------------------------------------------------
__global__ __launch_bounds__(256) void gp_kernel(float* __restrict__ out)
{
    const int s0  = blockIdx.x * STILE;
    const int b   = blockIdx.y;
    const int tid = threadIdx.x;

    float q[STILE][8];
#pragma unroll
    for (int si = 0; si < STILE; si++) {
        const float4 qa = *reinterpret_cast<const float4*>(&g_qk[0][b][s0 + si][0]);
        const float4 qb = *reinterpret_cast<const float4*>(&g_qk[0][b][s0 + si][4]);
        q[si][0] = qa.x; q[si][1] = qa.y; q[si][2] = qa.z; q[si][3] = qa.w;
        q[si][4] = qb.x; q[si][5] = qb.y; q[si][6] = qb.z; q[si][7] = qb.w;
    }

    const float* K = &g_qk[1][b][0][0];
    float* obase = out + (((size_t)b * S + s0) * S) * 8;

#pragma unroll
    for (int it = 0; it < 8; it++) {
        const int t = tid + it * 256;
        float4 ka, kb;
        ldg256(K + (size_t)t * 8, ka, kb);
        const float k0 = ka.x, k1 = ka.y, k2 = ka.z, k3 = ka.w;
        const float k4 = kb.x, k5 = kb.y, k6 = kb.z, k7 = kb.w;

#pragma unroll
        for (int si = 0; si < STILE; si++) {
            const float q0 = q[si][0], q1 = q[si][1], q2 = q[si][2], q3 = q[si][3];
            const float q4 = q[si][4], q5 = q[si][5], q6 = q[si][6], q7 = q[si][7];

            float4 o_lo, o_hi;
            o_lo.x = q0*k0 + q1*k1 + q2*k2 + q3*k3 - q4*k4 - q5*k5 - q6*k6 - q7*k7;
            o_lo.y = q0*k1 + q1*k0 - q2*k4 + q4*k2 - q3*k5 + q5*k3 - q6*k7 - q7*k6;
            o_lo.z = q0*k2 + q2*k0 + q1*k4 - q4*k1 - q3*k6 + q6*k3 + q5*k7 + q7*k5;
            o_lo.w = q0*k3 + q3*k0 + q1*k5 - q5*k1 + q2*k6 - q6*k2 - q4*k7 - q7*k4;
            o_hi.x = q0*k4 + q4*k0 + q1*k2 - q2*k1 + q3*k7 + q7*k3 - q5*k6 + q6*k5;
            o_hi.y = q0*k5 + q5*k0 + q1*k3 - q3*k1 - q2*k7 - q7*k2 + q4*k6 - q6*k4;
            o_hi.z = q0*k6 + q6*k0 + q2*k3 - q3*k2 + q1*k7 + q7*k1 - q4*k5 + q5*k4;
            o_hi.w = q0*k7 + q7*k0 + q1*k6 + q6*k1 - q2*k5 - q5*k2 + q3*k4 + q4*k3;

            stg256_cs(obase + (size_t)si * S * 8 + t * 8, o_lo, o_hi);
        }
    }
}

extern "C" void kernel_launch(void* const* d_in, const int* in_sizes, int n_in,
                              void* d_out, int out_size)
{
    const float* x  = (const float*)d_in[0];   // (2, 2048, 8)
    const float* Wq = (const float*)d_in[1];   // (2048, 2048, 4)
    const float* Wk = (const float*)d_in[2];   // (2048, 2048, 4)
    const float* a  = (const float*)d_in[3];   // (3000, 4)
    float* out = (float*)d_out;                // (2, 2048, 2048, 8)

    qk_main<<<QK_BLOCKS, QK_THREADS>>>(x, Wq, Wk);
    qk_fix<<<S / 8, 256>>>(a);
    gp_kernel<<<dim3(S / STILE, B), 256>>>(out);
}

// round 10
// speedup vs baseline: 1.1370x; 1.0426x over previous
#include <cuda_runtime.h>
#include <math.h>

#define S 2048
#define B 2
#define STILE 4
#define QK_THREADS 512
#define QK_BLOCKS 148
#define MAX_ROWS 14   // ceil(S / QK_BLOCKS)

// Normalized q and k: [which(q=0,k=1)][b][n][blade] = 256 KB
__device__ __align__(256) float g_qk[2][B][S][8];

// 256-bit global store, streaming (evict-first): output is never re-read.
__device__ __forceinline__ void stg256_cs(float* p, const float4& a, const float4& b)
{
    asm volatile("st.global.cs.v8.f32 [%0], {%1,%2,%3,%4,%5,%6,%7,%8};"
                 :: "l"(p),
                    "f"(a.x), "f"(a.y), "f"(a.z), "f"(a.w),
                    "f"(b.x), "f"(b.y), "f"(b.z), "f"(b.w)
                 : "memory");
}

__device__ __forceinline__ void ldg256(const float* p, float4& a, float4& b)
{
    asm volatile("ld.global.nc.v8.f32 {%0,%1,%2,%3,%4,%5,%6,%7}, [%8];"
                 : "=f"(a.x), "=f"(a.y), "=f"(a.z), "=f"(a.w),
                   "=f"(b.x), "=f"(b.y), "=f"(b.z), "=f"(b.w)
                 : "l"(p));
}

// ---------------------------------------------------------------------------
// Kernel 1 (persistent, barrier-free hot loop, fused fixup tail):
// 148 blocks x 512 threads; thread t owns m in [4t, 4t+4); x register-
// resident; cross-row W prefetch. Per-warp partials staged in SMEM; after
// the row loop, ONE __syncthreads and each warp normalizes one row.
// ---------------------------------------------------------------------------
__global__ __launch_bounds__(QK_THREADS) void qk_main(
    const float* __restrict__ x,    // (B, S, 8)
    const float* __restrict__ Wq,   // (S, S, 4)
    const float* __restrict__ Wk,   // (S, S, 4)
    const float* __restrict__ a)    // (3000, 4)
{
    const int tid  = threadIdx.x;
    const int warp = tid >> 5, lane = tid & 31;
    const int m0   = tid * 4;

    __shared__ float part[MAX_ROWS][16][32];

    // x slice: xr[j][0..1] = x[b0][m0+j], xr[j][2..3] = x[b1][m0+j]
    float4 xr[4][4];
#pragma unroll
    for (int j = 0; j < 4; j++) {
        ldg256(x + (size_t)(m0 + j) * 8,     xr[j][0], xr[j][1]);
        ldg256(x + (size_t)(S + m0 + j) * 8, xr[j][2], xr[j][3]);
    }

    const size_t coff = (size_t)m0 * 4;

    // Preload first row's W
    float4 wq[4], wk[4];
    {
        const float* WqR = Wq + (size_t)blockIdx.x * S * 4 + coff;
        const float* WkR = Wk + (size_t)blockIdx.x * S * 4 + coff;
        ldg256(WqR,     wq[0], wq[1]);
        ldg256(WqR + 8, wq[2], wq[3]);
        ldg256(WkR,     wk[0], wk[1]);
        ldg256(WkR + 8, wk[2], wk[3]);
    }

    int r = 0;
    for (int n = blockIdx.x; n < S; n += QK_BLOCKS, r++) {
        const int nn = n + QK_BLOCKS;

        // ---- q phase: v[0..7]=b0 blades, v[8..15]=b1 blades ----
        float v[16];
#pragma unroll
        for (int i = 0; i < 16; i++) v[i] = 0.f;
#pragma unroll
        for (int j = 0; j < 4; j++) {
            const float4 x0a = xr[j][0], x0b = xr[j][1];
            const float4 x1a = xr[j][2], x1b = xr[j][3];
            const float4 w = wq[j];
            v[0]  = fmaf(w.x, x0a.x, v[0]);
            v[1]  = fmaf(w.y, x0a.y, v[1]);
            v[2]  = fmaf(w.y, x0a.z, v[2]);
            v[3]  = fmaf(w.y, x0a.w, v[3]);
            v[4]  = fmaf(w.z, x0b.x, v[4]);
            v[5]  = fmaf(w.z, x0b.y, v[5]);
            v[6]  = fmaf(w.z, x0b.z, v[6]);
            v[7]  = fmaf(w.w, x0b.w, v[7]);
            v[8]  = fmaf(w.x, x1a.x, v[8]);
            v[9]  = fmaf(w.y, x1a.y, v[9]);
            v[10] = fmaf(w.y, x1a.z, v[10]);
            v[11] = fmaf(w.y, x1a.w, v[11]);
            v[12] = fmaf(w.z, x1b.x, v[12]);
            v[13] = fmaf(w.z, x1b.y, v[13]);
            v[14] = fmaf(w.z, x1b.z, v[14]);
            v[15] = fmaf(w.w, x1b.w, v[15]);
        }

        // PREFETCH next row's Wq (wq regs dead after q-FMAs)
        if (nn < S) {
            const float* WqR = Wq + (size_t)nn * S * 4 + coff;
            ldg256(WqR,     wq[0], wq[1]);
            ldg256(WqR + 8, wq[2], wq[3]);
        }

        // 16-value butterfly; final xor-16 merges halves -> full warp sum.
#pragma unroll
        for (int d = 8; d >= 1; d >>= 1) {
#pragma unroll
            for (int i = 0; i < d; i++) {
                const bool hi = (lane & d) != 0;
                const float keep = hi ? v[i + d] : v[i];
                const float send = hi ? v[i] : v[i + d];
                v[i] = keep + __shfl_xor_sync(0xffffffffu, send, d);
            }
        }
        v[0] += __shfl_xor_sync(0xffffffffu, v[0], 16);
        if (lane < 16) part[r][warp][lane] = v[0];

        // ---- k phase ----
#pragma unroll
        for (int i = 0; i < 16; i++) v[i] = 0.f;
#pragma unroll
        for (int j = 0; j < 4; j++) {
            const float4 x0a = xr[j][0], x0b = xr[j][1];
            const float4 x1a = xr[j][2], x1b = xr[j][3];
            const float4 w = wk[j];
            v[0]  = fmaf(w.x, x0a.x, v[0]);
            v[1]  = fmaf(w.y, x0a.y, v[1]);
            v[2]  = fmaf(w.y, x0a.z, v[2]);
            v[3]  = fmaf(w.y, x0a.w, v[3]);
            v[4]  = fmaf(w.z, x0b.x, v[4]);
            v[5]  = fmaf(w.z, x0b.y, v[5]);
            v[6]  = fmaf(w.z, x0b.z, v[6]);
            v[7]  = fmaf(w.w, x0b.w, v[7]);
            v[8]  = fmaf(w.x, x1a.x, v[8]);
            v[9]  = fmaf(w.y, x1a.y, v[9]);
            v[10] = fmaf(w.y, x1a.z, v[10]);
            v[11] = fmaf(w.y, x1a.w, v[11]);
            v[12] = fmaf(w.z, x1b.x, v[12]);
            v[13] = fmaf(w.z, x1b.y, v[13]);
            v[14] = fmaf(w.z, x1b.z, v[14]);
            v[15] = fmaf(w.w, x1b.w, v[15]);
        }

        // PREFETCH next row's Wk (wk regs dead after k-FMAs)
        if (nn < S) {
            const float* WkR = Wk + (size_t)nn * S * 4 + coff;
            ldg256(WkR,     wk[0], wk[1]);
            ldg256(WkR + 8, wk[2], wk[3]);
        }

#pragma unroll
        for (int d = 8; d >= 1; d >>= 1) {
#pragma unroll
            for (int i = 0; i < d; i++) {
                const bool hi = (lane & d) != 0;
                const float keep = hi ? v[i + d] : v[i];
                const float send = hi ? v[i] : v[i + d];
                v[i] = keep + __shfl_xor_sync(0xffffffffu, send, d);
            }
        }
        v[0] += __shfl_xor_sync(0xffffffffu, v[0], 16);
        if (lane < 16) part[r][warp][16 + lane] = v[0];
    }

    // ---- Fused fixup: one barrier, then warp w normalizes local row w ----
    __syncthreads();
    const int nrows = r;
    if (warp < nrows) {
        const int n = blockIdx.x + warp * QK_BLOCKS;

        float s = 0.f;
#pragma unroll
        for (int p = 0; p < 16; p++) s += part[warp][p][lane];

        // Gather the 8 blade values of this lane's (which,b) group.
        const int base = lane & ~7;
        const float e0 = __shfl_sync(0xffffffffu, s, base + 0);
        const float e1 = __shfl_sync(0xffffffffu, s, base + 1);
        const float e2 = __shfl_sync(0xffffffffu, s, base + 2);
        const float e3 = __shfl_sync(0xffffffffu, s, base + 3);
        const float e4 = __shfl_sync(0xffffffffu, s, base + 4);
        const float e5 = __shfl_sync(0xffffffffu, s, base + 5);
        const float e6 = __shfl_sync(0xffffffffu, s, base + 6);
        const float e7 = __shfl_sync(0xffffffffu, s, base + 7);

        const int i = lane & 7;
        const int g = (i == 0) ? 0 : (i < 4) ? 1 : (i < 7) ? 2 : 3;

        float nr;
        if      (g == 0) nr = fabsf(e0);
        else if (g == 1) nr = sqrtf(e1 * e1 + e2 * e2 + e3 * e3);
        else if (g == 2) nr = sqrtf(e4 * e4 + e5 * e5 + e6 * e6);
        else             nr = fabsf(e7);

        const float sa = 1.f / (1.f + expf(-a[n * 4 + g]));
        const float den = sa * (nr - 1.f) + 1.f + 1e-6f;

        const int which = lane >> 4, b = (lane >> 3) & 1;
        g_qk[which][b][n][i] = s / den;
    }
}

// ---------------------------------------------------------------------------
// Kernel 2: out[b,s,t,:] = q[b,s,:] (geometric product) k[b,t,:]
// 256-bit K loads, 256-bit streaming stores.
// ---------------------------------------------------------------------------
__global__ __launch_bounds__(256) void gp_kernel(float* __restrict__ out)
{
    const int s0  = blockIdx.x * STILE;
    const int b   = blockIdx.y;
    const int tid = threadIdx.x;

    float q[STILE][8];
#pragma unroll
    for (int si = 0; si < STILE; si++) {
        const float4 qa = *reinterpret_cast<const float4*>(&g_qk[0][b][s0 + si][0]);
        const float4 qb = *reinterpret_cast<const float4*>(&g_qk[0][b][s0 + si][4]);
        q[si][0] = qa.x; q[si][1] = qa.y; q[si][2] = qa.z; q[si][3] = qa.w;
        q[si][4] = qb.x; q[si][5] = qb.y; q[si][6] = qb.z; q[si][7] = qb.w;
    }

    const float* K = &g_qk[1][b][0][0];
    float* obase = out + (((size_t)b * S + s0) * S) * 8;

#pragma unroll
    for (int it = 0; it < 8; it++) {
        const int t = tid + it * 256;
        float4 ka, kb;
        ldg256(K + (size_t)t * 8, ka, kb);
        const float k0 = ka.x, k1 = ka.y, k2 = ka.z, k3 = ka.w;
        const float k4 = kb.x, k5 = kb.y, k6 = kb.z, k7 = kb.w;

#pragma unroll
        for (int si = 0; si < STILE; si++) {
            const float q0 = q[si][0], q1 = q[si][1], q2 = q[si][2], q3 = q[si][3];
            const float q4 = q[si][4], q5 = q[si][5], q6 = q[si][6], q7 = q[si][7];

            float4 o_lo, o_hi;
            o_lo.x = q0*k0 + q1*k1 + q2*k2 + q3*k3 - q4*k4 - q5*k5 - q6*k6 - q7*k7;
            o_lo.y = q0*k1 + q1*k0 - q2*k4 + q4*k2 - q3*k5 + q5*k3 - q6*k7 - q7*k6;
            o_lo.z = q0*k2 + q2*k0 + q1*k4 - q4*k1 - q3*k6 + q6*k3 + q5*k7 + q7*k5;
            o_lo.w = q0*k3 + q3*k0 + q1*k5 - q5*k1 + q2*k6 - q6*k2 - q4*k7 - q7*k4;
            o_hi.x = q0*k4 + q4*k0 + q1*k2 - q2*k1 + q3*k7 + q7*k3 - q5*k6 + q6*k5;
            o_hi.y = q0*k5 + q5*k0 + q1*k3 - q3*k1 - q2*k7 - q7*k2 + q4*k6 - q6*k4;
            o_hi.z = q0*k6 + q6*k0 + q2*k3 - q3*k2 + q1*k7 + q7*k1 - q4*k5 + q5*k4;
            o_hi.w = q0*k7 + q7*k0 + q1*k6 + q6*k1 - q2*k5 - q5*k2 + q3*k4 + q4*k3;

            stg256_cs(obase + (size_t)si * S * 8 + t * 8, o_lo, o_hi);
        }
    }
}

extern "C" void kernel_launch(void* const* d_in, const int* in_sizes, int n_in,
                              void* d_out, int out_size)
{
    const float* x  = (const float*)d_in[0];   // (2, 2048, 8)
    const float* Wq = (const float*)d_in[1];   // (2048, 2048, 4)
    const float* Wk = (const float*)d_in[2];   // (2048, 2048, 4)
    const float* a  = (const float*)d_in[3];   // (3000, 4)
    float* out = (float*)d_out;                // (2, 2048, 2048, 8)

    qk_main<<<QK_BLOCKS, QK_THREADS>>>(x, Wq, Wk, a);
    gp_kernel<<<dim3(S / STILE, B), 256>>>(out);
}

// round 11
// speedup vs baseline: 1.1422x; 1.0046x over previous
#include <cuda_runtime.h>
#include <math.h>

#define S 2048
#define B 2
#define STILE 4
#define QK_THREADS 512
#define QK_BLOCKS 148
#define MAX_ROWS 14   // ceil(S / QK_BLOCKS)

// Normalized q and k: [which(q=0,k=1)][b][n][blade] = 256 KB
__device__ __align__(256) float g_qk[2][B][S][8];

// 256-bit global store, streaming (evict-first): output is never re-read.
__device__ __forceinline__ void stg256_cs(float* p, const float4& a, const float4& b)
{
    asm volatile("st.global.cs.v8.f32 [%0], {%1,%2,%3,%4,%5,%6,%7,%8};"
                 :: "l"(p),
                    "f"(a.x), "f"(a.y), "f"(a.z), "f"(a.w),
                    "f"(b.x), "f"(b.y), "f"(b.z), "f"(b.w)
                 : "memory");
}

__device__ __forceinline__ void ldg256(const float* p, float4& a, float4& b)
{
    asm volatile("ld.global.nc.v8.f32 {%0,%1,%2,%3,%4,%5,%6,%7}, [%8];"
                 : "=f"(a.x), "=f"(a.y), "=f"(a.z), "=f"(a.w),
                   "=f"(b.x), "=f"(b.y), "=f"(b.z), "=f"(b.w)
                 : "l"(p));
}

// ---------------------------------------------------------------------------
// Kernel 1 (persistent, barrier-free hot loop, fused fixup tail):
// 148 blocks x 512 threads; thread t owns m in [4t, 4t+4); x register-
// resident; cross-row W prefetch. Per-warp partials staged in SMEM; after
// the row loop, ONE __syncthreads and each warp normalizes one row.
// ---------------------------------------------------------------------------
__global__ __launch_bounds__(QK_THREADS) void qk_main(
    const float* __restrict__ x,    // (B, S, 8)
    const float* __restrict__ Wq,   // (S, S, 4)
    const float* __restrict__ Wk,   // (S, S, 4)
    const float* __restrict__ a)    // (3000, 4)
{
    const int tid  = threadIdx.x;
    const int warp = tid >> 5, lane = tid & 31;
    const int m0   = tid * 4;

    __shared__ float part[MAX_ROWS][16][32];

    // x slice: xr[j][0..1] = x[b0][m0+j], xr[j][2..3] = x[b1][m0+j]
    float4 xr[4][4];
#pragma unroll
    for (int j = 0; j < 4; j++) {
        ldg256(x + (size_t)(m0 + j) * 8,     xr[j][0], xr[j][1]);
        ldg256(x + (size_t)(S + m0 + j) * 8, xr[j][2], xr[j][3]);
    }

    const size_t coff = (size_t)m0 * 4;

    // Preload first row's W
    float4 wq[4], wk[4];
    {
        const float* WqR = Wq + (size_t)blockIdx.x * S * 4 + coff;
        const float* WkR = Wk + (size_t)blockIdx.x * S * 4 + coff;
        ldg256(WqR,     wq[0], wq[1]);
        ldg256(WqR + 8, wq[2], wq[3]);
        ldg256(WkR,     wk[0], wk[1]);
        ldg256(WkR + 8, wk[2], wk[3]);
    }

    int r = 0;
    for (int n = blockIdx.x; n < S; n += QK_BLOCKS, r++) {
        const int nn = n + QK_BLOCKS;

        // ---- q phase: v[0..7]=b0 blades, v[8..15]=b1 blades ----
        float v[16];
#pragma unroll
        for (int i = 0; i < 16; i++) v[i] = 0.f;
#pragma unroll
        for (int j = 0; j < 4; j++) {
            const float4 x0a = xr[j][0], x0b = xr[j][1];
            const float4 x1a = xr[j][2], x1b = xr[j][3];
            const float4 w = wq[j];
            v[0]  = fmaf(w.x, x0a.x, v[0]);
            v[1]  = fmaf(w.y, x0a.y, v[1]);
            v[2]  = fmaf(w.y, x0a.z, v[2]);
            v[3]  = fmaf(w.y, x0a.w, v[3]);
            v[4]  = fmaf(w.z, x0b.x, v[4]);
            v[5]  = fmaf(w.z, x0b.y, v[5]);
            v[6]  = fmaf(w.z, x0b.z, v[6]);
            v[7]  = fmaf(w.w, x0b.w, v[7]);
            v[8]  = fmaf(w.x, x1a.x, v[8]);
            v[9]  = fmaf(w.y, x1a.y, v[9]);
            v[10] = fmaf(w.y, x1a.z, v[10]);
            v[11] = fmaf(w.y, x1a.w, v[11]);
            v[12] = fmaf(w.z, x1b.x, v[12]);
            v[13] = fmaf(w.z, x1b.y, v[13]);
            v[14] = fmaf(w.z, x1b.z, v[14]);
            v[15] = fmaf(w.w, x1b.w, v[15]);
        }

        // PREFETCH next row's Wq (wq regs dead after q-FMAs)
        if (nn < S) {
            const float* WqR = Wq + (size_t)nn * S * 4 + coff;
            ldg256(WqR,     wq[0], wq[1]);
            ldg256(WqR + 8, wq[2], wq[3]);
        }

        // 16-value butterfly; final xor-16 merges halves -> full warp sum.
#pragma unroll
        for (int d = 8; d >= 1; d >>= 1) {
#pragma unroll
            for (int i = 0; i < d; i++) {
                const bool hi = (lane & d) != 0;
                const float keep = hi ? v[i + d] : v[i];
                const float send = hi ? v[i] : v[i + d];
                v[i] = keep + __shfl_xor_sync(0xffffffffu, send, d);
            }
        }
        v[0] += __shfl_xor_sync(0xffffffffu, v[0], 16);
        if (lane < 16) part[r][warp][lane] = v[0];

        // ---- k phase ----
#pragma unroll
        for (int i = 0; i < 16; i++) v[i] = 0.f;
#pragma unroll
        for (int j = 0; j < 4; j++) {
            const float4 x0a = xr[j][0], x0b = xr[j][1];
            const float4 x1a = xr[j][2], x1b = xr[j][3];
            const float4 w = wk[j];
            v[0]  = fmaf(w.x, x0a.x, v[0]);
            v[1]  = fmaf(w.y, x0a.y, v[1]);
            v[2]  = fmaf(w.y, x0a.z, v[2]);
            v[3]  = fmaf(w.y, x0a.w, v[3]);
            v[4]  = fmaf(w.z, x0b.x, v[4]);
            v[5]  = fmaf(w.z, x0b.y, v[5]);
            v[6]  = fmaf(w.z, x0b.z, v[6]);
            v[7]  = fmaf(w.w, x0b.w, v[7]);
            v[8]  = fmaf(w.x, x1a.x, v[8]);
            v[9]  = fmaf(w.y, x1a.y, v[9]);
            v[10] = fmaf(w.y, x1a.z, v[10]);
            v[11] = fmaf(w.y, x1a.w, v[11]);
            v[12] = fmaf(w.z, x1b.x, v[12]);
            v[13] = fmaf(w.z, x1b.y, v[13]);
            v[14] = fmaf(w.z, x1b.z, v[14]);
            v[15] = fmaf(w.w, x1b.w, v[15]);
        }

        // PREFETCH next row's Wk (wk regs dead after k-FMAs)
        if (nn < S) {
            const float* WkR = Wk + (size_t)nn * S * 4 + coff;
            ldg256(WkR,     wk[0], wk[1]);
            ldg256(WkR + 8, wk[2], wk[3]);
        }

#pragma unroll
        for (int d = 8; d >= 1; d >>= 1) {
#pragma unroll
            for (int i = 0; i < d; i++) {
                const bool hi = (lane & d) != 0;
                const float keep = hi ? v[i + d] : v[i];
                const float send = hi ? v[i] : v[i + d];
                v[i] = keep + __shfl_xor_sync(0xffffffffu, send, d);
            }
        }
        v[0] += __shfl_xor_sync(0xffffffffu, v[0], 16);
        if (lane < 16) part[r][warp][16 + lane] = v[0];
    }

    // ---- Fused fixup: one barrier, then warp w normalizes local row w ----
    __syncthreads();
    const int nrows = r;
    if (warp < nrows) {
        const int n = blockIdx.x + warp * QK_BLOCKS;

        float s = 0.f;
#pragma unroll
        for (int p = 0; p < 16; p++) s += part[warp][p][lane];

        // Gather the 8 blade values of this lane's (which,b) group.
        const int base = lane & ~7;
        const float e0 = __shfl_sync(0xffffffffu, s, base + 0);
        const float e1 = __shfl_sync(0xffffffffu, s, base + 1);
        const float e2 = __shfl_sync(0xffffffffu, s, base + 2);
        const float e3 = __shfl_sync(0xffffffffu, s, base + 3);
        const float e4 = __shfl_sync(0xffffffffu, s, base + 4);
        const float e5 = __shfl_sync(0xffffffffu, s, base + 5);
        const float e6 = __shfl_sync(0xffffffffu, s, base + 6);
        const float e7 = __shfl_sync(0xffffffffu, s, base + 7);

        const int i = lane & 7;
        const int g = (i == 0) ? 0 : (i < 4) ? 1 : (i < 7) ? 2 : 3;

        float nr;
        if      (g == 0) nr = fabsf(e0);
        else if (g == 1) nr = sqrtf(e1 * e1 + e2 * e2 + e3 * e3);
        else if (g == 2) nr = sqrtf(e4 * e4 + e5 * e5 + e6 * e6);
        else             nr = fabsf(e7);

        const float sa = 1.f / (1.f + expf(-a[n * 4 + g]));
        const float den = sa * (nr - 1.f) + 1.f + 1e-6f;

        const int which = lane >> 4, b = (lane >> 3) & 1;
        g_qk[which][b][n][i] = s / den;
    }
}

// ---------------------------------------------------------------------------
// Kernel 2: out[b,s,t,:] = q[b,s,:] (geometric product) k[b,t,:]
// K loads DOUBLE-BUFFERED (next iteration's K issued before this
// iteration's FMA/store block) so L2-hit latency is off the critical path.
// ---------------------------------------------------------------------------
__global__ __launch_bounds__(256) void gp_kernel(float* __restrict__ out)
{
    const int s0  = blockIdx.x * STILE;
    const int b   = blockIdx.y;
    const int tid = threadIdx.x;

    float q[STILE][8];
#pragma unroll
    for (int si = 0; si < STILE; si++) {
        const float4 qa = *reinterpret_cast<const float4*>(&g_qk[0][b][s0 + si][0]);
        const float4 qb = *reinterpret_cast<const float4*>(&g_qk[0][b][s0 + si][4]);
        q[si][0] = qa.x; q[si][1] = qa.y; q[si][2] = qa.z; q[si][3] = qa.w;
        q[si][4] = qb.x; q[si][5] = qb.y; q[si][6] = qb.z; q[si][7] = qb.w;
    }

    const float* K = &g_qk[1][b][0][0];
    float* obase = out + (((size_t)b * S + s0) * S) * 8;

    // Preload iteration 0's K
    float4 ka, kb;
    ldg256(K + (size_t)tid * 8, ka, kb);

#pragma unroll
    for (int it = 0; it < 8; it++) {
        const int t = tid + it * 256;

        // Prefetch next iteration's K before consuming this one.
        float4 ka_n, kb_n;
        if (it < 7) ldg256(K + (size_t)(t + 256) * 8, ka_n, kb_n);

        const float k0 = ka.x, k1 = ka.y, k2 = ka.z, k3 = ka.w;
        const float k4 = kb.x, k5 = kb.y, k6 = kb.z, k7 = kb.w;

#pragma unroll
        for (int si = 0; si < STILE; si++) {
            const float q0 = q[si][0], q1 = q[si][1], q2 = q[si][2], q3 = q[si][3];
            const float q4 = q[si][4], q5 = q[si][5], q6 = q[si][6], q7 = q[si][7];

            float4 o_lo, o_hi;
            o_lo.x = q0*k0 + q1*k1 + q2*k2 + q3*k3 - q4*k4 - q5*k5 - q6*k6 - q7*k7;
            o_lo.y = q0*k1 + q1*k0 - q2*k4 + q4*k2 - q3*k5 + q5*k3 - q6*k7 - q7*k6;
            o_lo.z = q0*k2 + q2*k0 + q1*k4 - q4*k1 - q3*k6 + q6*k3 + q5*k7 + q7*k5;
            o_lo.w = q0*k3 + q3*k0 + q1*k5 - q5*k1 + q2*k6 - q6*k2 - q4*k7 - q7*k4;
            o_hi.x = q0*k4 + q4*k0 + q1*k2 - q2*k1 + q3*k7 + q7*k3 - q5*k6 + q6*k5;
            o_hi.y = q0*k5 + q5*k0 + q1*k3 - q3*k1 - q2*k7 - q7*k2 + q4*k6 - q6*k4;
            o_hi.z = q0*k6 + q6*k0 + q2*k3 - q3*k2 + q1*k7 + q7*k1 - q4*k5 + q5*k4;
            o_hi.w = q0*k7 + q7*k0 + q1*k6 + q6*k1 - q2*k5 - q5*k2 + q3*k4 + q4*k3;

            stg256_cs(obase + (size_t)si * S * 8 + t * 8, o_lo, o_hi);
        }

        ka = ka_n; kb = kb_n;
    }
}

extern "C" void kernel_launch(void* const* d_in, const int* in_sizes, int n_in,
                              void* d_out, int out_size)
{
    const float* x  = (const float*)d_in[0];   // (2, 2048, 8)
    const float* Wq = (const float*)d_in[1];   // (2048, 2048, 4)
    const float* Wk = (const float*)d_in[2];   // (2048, 2048, 4)
    const float* a  = (const float*)d_in[3];   // (3000, 4)
    float* out = (float*)d_out;                // (2, 2048, 2048, 8)

    qk_main<<<QK_BLOCKS, QK_THREADS>>>(x, Wq, Wk, a);
    gp_kernel<<<dim3(S / STILE, B), 256>>>(out);
}

// round 12
// speedup vs baseline: 1.1737x; 1.0276x over previous
#include <cuda_runtime.h>
#include <math.h>

#define S 2048
#define B 2
#define STILE 2
#define QK_THREADS 512
#define QK_BLOCKS 148
#define MAX_ROWS 14   // ceil(S / QK_BLOCKS)

// Normalized q and k: [which(q=0,k=1)][b][n][blade] = 256 KB
__device__ __align__(256) float g_qk[2][B][S][8];

// 256-bit global store, streaming (evict-first): output is never re-read.
__device__ __forceinline__ void stg256_cs(float* p, const float4& a, const float4& b)
{
    asm volatile("st.global.cs.v8.f32 [%0], {%1,%2,%3,%4,%5,%6,%7,%8};"
                 :: "l"(p),
                    "f"(a.x), "f"(a.y), "f"(a.z), "f"(a.w),
                    "f"(b.x), "f"(b.y), "f"(b.z), "f"(b.w)
                 : "memory");
}

__device__ __forceinline__ void ldg256(const float* p, float4& a, float4& b)
{
    asm volatile("ld.global.nc.v8.f32 {%0,%1,%2,%3,%4,%5,%6,%7}, [%8];"
                 : "=f"(a.x), "=f"(a.y), "=f"(a.z), "=f"(a.w),
                   "=f"(b.x), "=f"(b.y), "=f"(b.z), "=f"(b.w)
                 : "l"(p));
}

// ---------------------------------------------------------------------------
// Kernel 1 (persistent, barrier-free hot loop, fused fixup tail):
// 148 blocks x 512 threads; thread t owns m in [4t, 4t+4); x register-
// resident; cross-row W prefetch. Per-warp partials staged in SMEM; after
// the row loop, ONE __syncthreads and each warp normalizes one row.
// ---------------------------------------------------------------------------
__global__ __launch_bounds__(QK_THREADS) void qk_main(
    const float* __restrict__ x,    // (B, S, 8)
    const float* __restrict__ Wq,   // (S, S, 4)
    const float* __restrict__ Wk,   // (S, S, 4)
    const float* __restrict__ a)    // (3000, 4)
{
    const int tid  = threadIdx.x;
    const int warp = tid >> 5, lane = tid & 31;
    const int m0   = tid * 4;

    __shared__ float part[MAX_ROWS][16][32];

    // x slice: xr[j][0..1] = x[b0][m0+j], xr[j][2..3] = x[b1][m0+j]
    float4 xr[4][4];
#pragma unroll
    for (int j = 0; j < 4; j++) {
        ldg256(x + (size_t)(m0 + j) * 8,     xr[j][0], xr[j][1]);
        ldg256(x + (size_t)(S + m0 + j) * 8, xr[j][2], xr[j][3]);
    }

    const size_t coff = (size_t)m0 * 4;

    // Preload first row's W
    float4 wq[4], wk[4];
    {
        const float* WqR = Wq + (size_t)blockIdx.x * S * 4 + coff;
        const float* WkR = Wk + (size_t)blockIdx.x * S * 4 + coff;
        ldg256(WqR,     wq[0], wq[1]);
        ldg256(WqR + 8, wq[2], wq[3]);
        ldg256(WkR,     wk[0], wk[1]);
        ldg256(WkR + 8, wk[2], wk[3]);
    }

    int r = 0;
    for (int n = blockIdx.x; n < S; n += QK_BLOCKS, r++) {
        const int nn = n + QK_BLOCKS;

        // ---- q phase: v[0..7]=b0 blades, v[8..15]=b1 blades ----
        float v[16];
#pragma unroll
        for (int i = 0; i < 16; i++) v[i] = 0.f;
#pragma unroll
        for (int j = 0; j < 4; j++) {
            const float4 x0a = xr[j][0], x0b = xr[j][1];
            const float4 x1a = xr[j][2], x1b = xr[j][3];
            const float4 w = wq[j];
            v[0]  = fmaf(w.x, x0a.x, v[0]);
            v[1]  = fmaf(w.y, x0a.y, v[1]);
            v[2]  = fmaf(w.y, x0a.z, v[2]);
            v[3]  = fmaf(w.y, x0a.w, v[3]);
            v[4]  = fmaf(w.z, x0b.x, v[4]);
            v[5]  = fmaf(w.z, x0b.y, v[5]);
            v[6]  = fmaf(w.z, x0b.z, v[6]);
            v[7]  = fmaf(w.w, x0b.w, v[7]);
            v[8]  = fmaf(w.x, x1a.x, v[8]);
            v[9]  = fmaf(w.y, x1a.y, v[9]);
            v[10] = fmaf(w.y, x1a.z, v[10]);
            v[11] = fmaf(w.y, x1a.w, v[11]);
            v[12] = fmaf(w.z, x1b.x, v[12]);
            v[13] = fmaf(w.z, x1b.y, v[13]);
            v[14] = fmaf(w.z, x1b.z, v[14]);
            v[15] = fmaf(w.w, x1b.w, v[15]);
        }

        // PREFETCH next row's Wq (wq regs dead after q-FMAs)
        if (nn < S) {
            const float* WqR = Wq + (size_t)nn * S * 4 + coff;
            ldg256(WqR,     wq[0], wq[1]);
            ldg256(WqR + 8, wq[2], wq[3]);
        }

        // 16-value butterfly; final xor-16 merges halves -> full warp sum.
#pragma unroll
        for (int d = 8; d >= 1; d >>= 1) {
#pragma unroll
            for (int i = 0; i < d; i++) {
                const bool hi = (lane & d) != 0;
                const float keep = hi ? v[i + d] : v[i];
                const float send = hi ? v[i] : v[i + d];
                v[i] = keep + __shfl_xor_sync(0xffffffffu, send, d);
            }
        }
        v[0] += __shfl_xor_sync(0xffffffffu, v[0], 16);
        if (lane < 16) part[r][warp][lane] = v[0];

        // ---- k phase ----
#pragma unroll
        for (int i = 0; i < 16; i++) v[i] = 0.f;
#pragma unroll
        for (int j = 0; j < 4; j++) {
            const float4 x0a = xr[j][0], x0b = xr[j][1];
            const float4 x1a = xr[j][2], x1b = xr[j][3];
            const float4 w = wk[j];
            v[0]  = fmaf(w.x, x0a.x, v[0]);
            v[1]  = fmaf(w.y, x0a.y, v[1]);
            v[2]  = fmaf(w.y, x0a.z, v[2]);
            v[3]  = fmaf(w.y, x0a.w, v[3]);
            v[4]  = fmaf(w.z, x0b.x, v[4]);
            v[5]  = fmaf(w.z, x0b.y, v[5]);
            v[6]  = fmaf(w.z, x0b.z, v[6]);
            v[7]  = fmaf(w.w, x0b.w, v[7]);
            v[8]  = fmaf(w.x, x1a.x, v[8]);
            v[9]  = fmaf(w.y, x1a.y, v[9]);
            v[10] = fmaf(w.y, x1a.z, v[10]);
            v[11] = fmaf(w.y, x1a.w, v[11]);
            v[12] = fmaf(w.z, x1b.x, v[12]);
            v[13] = fmaf(w.z, x1b.y, v[13]);
            v[14] = fmaf(w.z, x1b.z, v[14]);
            v[15] = fmaf(w.w, x1b.w, v[15]);
        }

        // PREFETCH next row's Wk (wk regs dead after k-FMAs)
        if (nn < S) {
            const float* WkR = Wk + (size_t)nn * S * 4 + coff;
            ldg256(WkR,     wk[0], wk[1]);
            ldg256(WkR + 8, wk[2], wk[3]);
        }

#pragma unroll
        for (int d = 8; d >= 1; d >>= 1) {
#pragma unroll
            for (int i = 0; i < d; i++) {
                const bool hi = (lane & d) != 0;
                const float keep = hi ? v[i + d] : v[i];
                const float send = hi ? v[i] : v[i + d];
                v[i] = keep + __shfl_xor_sync(0xffffffffu, send, d);
            }
        }
        v[0] += __shfl_xor_sync(0xffffffffu, v[0], 16);
        if (lane < 16) part[r][warp][16 + lane] = v[0];
    }

    // ---- Fused fixup: one barrier, then warp w normalizes local row w ----
    __syncthreads();
    const int nrows = r;
    if (warp < nrows) {
        const int n = blockIdx.x + warp * QK_BLOCKS;

        float s = 0.f;
#pragma unroll
        for (int p = 0; p < 16; p++) s += part[warp][p][lane];

        // Gather the 8 blade values of this lane's (which,b) group.
        const int base = lane & ~7;
        const float e0 = __shfl_sync(0xffffffffu, s, base + 0);
        const float e1 = __shfl_sync(0xffffffffu, s, base + 1);
        const float e2 = __shfl_sync(0xffffffffu, s, base + 2);
        const float e3 = __shfl_sync(0xffffffffu, s, base + 3);
        const float e4 = __shfl_sync(0xffffffffu, s, base + 4);
        const float e5 = __shfl_sync(0xffffffffu, s, base + 5);
        const float e6 = __shfl_sync(0xffffffffu, s, base + 6);
        const float e7 = __shfl_sync(0xffffffffu, s, base + 7);

        const int i = lane & 7;
        const int g = (i == 0) ? 0 : (i < 4) ? 1 : (i < 7) ? 2 : 3;

        float nr;
        if      (g == 0) nr = fabsf(e0);
        else if (g == 1) nr = sqrtf(e1 * e1 + e2 * e2 + e3 * e3);
        else if (g == 2) nr = sqrtf(e4 * e4 + e5 * e5 + e6 * e6);
        else             nr = fabsf(e7);

        const float sa = 1.f / (1.f + expf(-a[n * 4 + g]));
        const float den = sa * (nr - 1.f) + 1.f + 1e-6f;

        const int which = lane >> 4, b = (lane >> 3) & 1;
        g_qk[which][b][n][i] = s / den;
    }
}

// ---------------------------------------------------------------------------
// Kernel 2: out[b,s,t,:] = q[b,s,:] (geometric product) k[b,t,:]
// STILE=2 + launch_bounds(256, 6): <=42 regs -> 6 blocks/SM = 48 warps,
// more concurrent store streams per SM.
// ---------------------------------------------------------------------------
__global__ __launch_bounds__(256, 6) void gp_kernel(float* __restrict__ out)
{
    const int s0  = blockIdx.x * STILE;
    const int b   = blockIdx.y;
    const int tid = threadIdx.x;

    float q[STILE][8];
#pragma unroll
    for (int si = 0; si < STILE; si++) {
        const float4 qa = *reinterpret_cast<const float4*>(&g_qk[0][b][s0 + si][0]);
        const float4 qb = *reinterpret_cast<const float4*>(&g_qk[0][b][s0 + si][4]);
        q[si][0] = qa.x; q[si][1] = qa.y; q[si][2] = qa.z; q[si][3] = qa.w;
        q[si][4] = qb.x; q[si][5] = qb.y; q[si][6] = qb.z; q[si][7] = qb.w;
    }

    const float* K = &g_qk[1][b][0][0];
    float* obase = out + (((size_t)b * S + s0) * S) * 8;

#pragma unroll
    for (int it = 0; it < 8; it++) {
        const int t = tid + it * 256;
        float4 ka, kb;
        ldg256(K + (size_t)t * 8, ka, kb);
        const float k0 = ka.x, k1 = ka.y, k2 = ka.z, k3 = ka.w;
        const float k4 = kb.x, k5 = kb.y, k6 = kb.z, k7 = kb.w;

#pragma unroll
        for (int si = 0; si < STILE; si++) {
            const float q0 = q[si][0], q1 = q[si][1], q2 = q[si][2], q3 = q[si][3];
            const float q4 = q[si][4], q5 = q[si][5], q6 = q[si][6], q7 = q[si][7];

            float4 o_lo, o_hi;
            o_lo.x = q0*k0 + q1*k1 + q2*k2 + q3*k3 - q4*k4 - q5*k5 - q6*k6 - q7*k7;
            o_lo.y = q0*k1 + q1*k0 - q2*k4 + q4*k2 - q3*k5 + q5*k3 - q6*k7 - q7*k6;
            o_lo.z = q0*k2 + q2*k0 + q1*k4 - q4*k1 - q3*k6 + q6*k3 + q5*k7 + q7*k5;
            o_lo.w = q0*k3 + q3*k0 + q1*k5 - q5*k1 + q2*k6 - q6*k2 - q4*k7 - q7*k4;
            o_hi.x = q0*k4 + q4*k0 + q1*k2 - q2*k1 + q3*k7 + q7*k3 - q5*k6 + q6*k5;
            o_hi.y = q0*k5 + q5*k0 + q1*k3 - q3*k1 - q2*k7 - q7*k2 + q4*k6 - q6*k4;
            o_hi.z = q0*k6 + q6*k0 + q2*k3 - q3*k2 + q1*k7 + q7*k1 - q4*k5 + q5*k4;
            o_hi.w = q0*k7 + q7*k0 + q1*k6 + q6*k1 - q2*k5 - q5*k2 + q3*k4 + q4*k3;

            stg256_cs(obase + (size_t)si * S * 8 + t * 8, o_lo, o_hi);
        }
    }
}

extern "C" void kernel_launch(void* const* d_in, const int* in_sizes, int n_in,
                              void* d_out, int out_size)
{
    const float* x  = (const float*)d_in[0];   // (2, 2048, 8)
    const float* Wq = (const float*)d_in[1];   // (2048, 2048, 4)
    const float* Wk = (const float*)d_in[2];   // (2048, 2048, 4)
    const float* a  = (const float*)d_in[3];   // (3000, 4)
    float* out = (float*)d_out;                // (2, 2048, 2048, 8)

    qk_main<<<QK_BLOCKS, QK_THREADS>>>(x, Wq, Wk, a);
    gp_kernel<<<dim3(S / STILE, B), 256>>>(out);
}